// round 5
// baseline (speedup 1.0000x reference)
#include <cuda_runtime.h>
#include <math.h>
#include <stdint.h>

// Problem constants
#define NUM_B   2
#define NUM_N   16384
#define NUM_DIN 1024
#define NUM_H   512
#define NUM_C   11
#define NUM_K   100
#define CAND    (NUM_N * (NUM_C - 1))   // 163840 candidates per frame
#define NCHUNK  (CAND / 64)             // 2560 chunks of 64
#define ROWS    (NUM_B * NUM_N)         // 32768

// ---------------- scratch (static device globals; no allocs) ----------------
__device__ float g_h1[(size_t)ROWS * NUM_H];
__device__ float g_h2[(size_t)ROWS * NUM_H];
__device__ float g_logits[(size_t)ROWS * NUM_C];
__device__ float g_reg[(size_t)ROWS * NUM_C * 9];
__device__ float4 g_box4[NUM_B * CAND];                  // class-major layout
__device__ float  g_box9[(size_t)NUM_B * CAND * 9];
__device__ float  g_raw[NUM_B * CAND];
__device__ float  g_mask[NUM_B * CAND];
__device__ unsigned int g_maxbits;

// ---------------- fp32 tiled GEMM: C = act(A[M,K] @ W[K,N] + bias) ----------
#define BM 128
#define BN 64
#define BK 16

__global__ __launch_bounds__(256)
void gemm_bias_relu(const float* __restrict__ A, const float* __restrict__ W,
                    const float* __restrict__ bias, float* __restrict__ C,
                    int M, int K, int N, int doRelu)
{
    __shared__ float As[BK][BM + 4];
    __shared__ float Ws[BK][BN];

    const int tid = threadIdx.x;
    const int bm = blockIdx.y * BM;
    const int bn = blockIdx.x * BN;
    const int tx = tid & 15;       // 16 col-groups of 4
    const int ty = tid >> 4;       // 16 row-groups of 8

    float acc[8][4];
#pragma unroll
    for (int i = 0; i < 8; i++)
#pragma unroll
        for (int j = 0; j < 4; j++) acc[i][j] = 0.0f;

    const int aRow = tid >> 2;           // 0..63
    const int aK   = (tid & 3) << 2;     // 0,4,8,12
    const int wRow = tid >> 4;           // 0..15
    const int wCol = (tid & 15) << 2;    // 0..60

    for (int k0 = 0; k0 < K; k0 += BK) {
        // A tile: 128 rows x 16 k, float4 loads, stored transposed
        float4 a0 = *(const float4*)(A + (size_t)(bm + aRow) * K + k0 + aK);
        float4 a1 = *(const float4*)(A + (size_t)(bm + aRow + 64) * K + k0 + aK);
        As[aK + 0][aRow] = a0.x; As[aK + 1][aRow] = a0.y;
        As[aK + 2][aRow] = a0.z; As[aK + 3][aRow] = a0.w;
        As[aK + 0][aRow + 64] = a1.x; As[aK + 1][aRow + 64] = a1.y;
        As[aK + 2][aRow + 64] = a1.z; As[aK + 3][aRow + 64] = a1.w;

        // W tile: 16 k-rows x 64 n-cols (vector path only when N%4==0 & in range)
        float wv0 = 0.f, wv1 = 0.f, wv2 = 0.f, wv3 = 0.f;
        const float* wrp = W + (size_t)(k0 + wRow) * N + bn + wCol;
        if (((N & 3) == 0) && (bn + wCol + 4 <= N)) {
            float4 t = *(const float4*)wrp;
            wv0 = t.x; wv1 = t.y; wv2 = t.z; wv3 = t.w;
        } else {
            if (bn + wCol + 0 < N) wv0 = wrp[0];
            if (bn + wCol + 1 < N) wv1 = wrp[1];
            if (bn + wCol + 2 < N) wv2 = wrp[2];
            if (bn + wCol + 3 < N) wv3 = wrp[3];
        }
        *(float4*)&Ws[wRow][wCol] = make_float4(wv0, wv1, wv2, wv3);

        __syncthreads();

#pragma unroll
        for (int kk = 0; kk < BK; kk++) {
            float4 aA = *(const float4*)&As[kk][ty * 8];
            float4 aB = *(const float4*)&As[kk][ty * 8 + 4];
            float4 bV = *(const float4*)&Ws[kk][tx * 4];
            float av[8] = {aA.x, aA.y, aA.z, aA.w, aB.x, aB.y, aB.z, aB.w};
            float bv[4] = {bV.x, bV.y, bV.z, bV.w};
#pragma unroll
            for (int i = 0; i < 8; i++)
#pragma unroll
                for (int j = 0; j < 4; j++)
                    acc[i][j] = fmaf(av[i], bv[j], acc[i][j]);
        }
        __syncthreads();
    }

#pragma unroll
    for (int i = 0; i < 8; i++) {
        int row = bm + ty * 8 + i;
#pragma unroll
        for (int j = 0; j < 4; j++) {
            int col = bn + tx * 4 + j;
            if (col < N) {
                float v = acc[i][j] + bias[col];
                if (doRelu) v = fmaxf(v, 0.0f);
                C[(size_t)row * N + col] = v;
            }
        }
    }
}

// ---------------- init ----------------
__global__ void init_kernel() { g_maxbits = 0u; }

// ---------------- softmax + box decode + candidate build ----------------
__global__ __launch_bounds__(256)
void decode_kernel(const float* __restrict__ proposals)
{
    const int tid = blockIdx.x * blockDim.x + threadIdx.x;   // < 327680
    const int c  = tid >> 15;        // class-1 index 0..9 (label = c+1)
    const int bn = tid & 32767;      // flat row
    const int b  = bn >> 14;
    const int n  = bn & 16383;

    // softmax over 11 logits
    const float* lrow = g_logits + (size_t)bn * NUM_C;
    float l[NUM_C];
#pragma unroll
    for (int i = 0; i < NUM_C; i++) l[i] = lrow[i];
    float m = l[0];
#pragma unroll
    for (int i = 1; i < NUM_C; i++) m = fmaxf(m, l[i]);
    float sum = 0.0f;
#pragma unroll
    for (int i = 0; i < NUM_C; i++) sum += expf(l[i] - m);
    float score = expf(l[c + 1] - m) / sum;

    // decode
    const float* p = proposals + (size_t)bn * 9;
    float w  = p[2] - p[0], h = p[3] - p[1];
    float cx = p[0] + 0.5f * w, cy = p[1] + 0.5f * h;
    const float* r = g_reg + (size_t)bn * (NUM_C * 9) + (c + 1) * 9;
    const float CLIP = 4.135166556742356f;  // log(1000/16)
    float dx = r[0] / 10.0f, dy = r[1] / 10.0f;
    float dw = fminf(r[2] / 5.0f, CLIP), dh = fminf(r[3] / 5.0f, CLIP);
    float pcx = dx * w + cx, pcy = dy * h + cy;
    float pw = expf(dw) * w, ph = expf(dh) * h;
    float x1 = pcx - 0.5f * pw, y1 = pcy - 0.5f * ph;
    float x2 = pcx + 0.5f * pw, y2 = pcy + 0.5f * ph;

    const int cand = b * CAND + c * NUM_N + n;   // class-major per frame
    g_box4[cand] = make_float4(x1, y1, x2, y2);
    float* b9 = g_box9 + (size_t)cand * 9;
    b9[0] = x1; b9[1] = y1; b9[2] = x2; b9[3] = y2;
#pragma unroll
    for (int j = 0; j < 5; j++) b9[4 + j] = p[4 + j] + r[4 + j];

    float bw = x2 - x1, bh = y2 - y1;
    bool valid = (score > 0.05f) && (bw >= 0.01f) && (bh >= 0.01f);
    g_raw[cand]  = score;
    g_mask[cand] = valid ? score : -INFINITY;

    // global max |coord| (order-independent => bitwise identical to reference's max)
    float mc = fmaxf(fmaxf(fabsf(x1), fabsf(y1)), fmaxf(fabsf(x2), fabsf(y2)));
#pragma unroll
    for (int o = 16; o; o >>= 1)
        mc = fmaxf(mc, __shfl_xor_sync(0xffffffffu, mc, o));
    if ((threadIdx.x & 31) == 0) atomicMax(&g_maxbits, __float_as_uint(mc));
}

// ---------------- greedy NMS (exact), one block per frame ----------------
__device__ __forceinline__ unsigned long long packkey(float v, unsigned idx) {
    unsigned u = __float_as_uint(v);
    u = (u & 0x80000000u) ? ~u : (u | 0x80000000u);   // order-preserving float map
    return ((unsigned long long)u << 32) | (unsigned long long)(0xFFFFFFFFu - idx);
}

__global__ __launch_bounds__(1024)
void nms_kernel(float* __restrict__ out)
{
    const int f = blockIdx.x;
    const int tid = threadIdx.x;

    __shared__ float chmax[NCHUNK];
    __shared__ unsigned long long warpKeys[32];
    __shared__ unsigned long long sBestKey;
    __shared__ int   sIdx[NUM_K];
    __shared__ float sVal[NUM_K];
    __shared__ float4 sPbox;
    __shared__ float sOffv;

    float* sc = g_mask + (size_t)f * CAND;
    const float4* bx = g_box4 + (size_t)f * CAND;
    const float maxc = __uint_as_float(g_maxbits);
    const float offUnit = maxc + 1.0f;

    // build per-chunk maxima
    for (int ch = tid; ch < NCHUNK; ch += 1024) {
        const float4* p4 = (const float4*)(sc + ch * 64);
        float m = -INFINITY;
#pragma unroll
        for (int j = 0; j < 16; j++) {
            float4 v = p4[j];
            m = fmaxf(m, fmaxf(fmaxf(v.x, v.y), fmaxf(v.z, v.w)));
        }
        chmax[ch] = m;
    }
    __syncthreads();

    for (int k = 0; k < NUM_K; k++) {
        // --- hierarchical argmax (lowest index wins ties) ---
        unsigned long long key = 0ull;
        for (int ch = tid; ch < NCHUNK; ch += 1024) {
            unsigned long long kk = packkey(chmax[ch], (unsigned)ch);
            if (kk > key) key = kk;
        }
#pragma unroll
        for (int o = 16; o; o >>= 1) {
            unsigned long long other = __shfl_xor_sync(0xffffffffu, key, o);
            if (other > key) key = other;
        }
        if ((tid & 31) == 0) warpKeys[tid >> 5] = key;
        __syncthreads();
        if (tid < 32) {
            unsigned long long kk = warpKeys[tid];
#pragma unroll
            for (int o = 16; o; o >>= 1) {
                unsigned long long other = __shfl_xor_sync(0xffffffffu, kk, o);
                if (other > kk) kk = other;
            }
            if (tid == 0) sBestKey = kk;
        }
        __syncthreads();
        const int bestCh = (int)(0xFFFFFFFFu - (unsigned)(sBestKey & 0xFFFFFFFFull));

        // rescan winning 64-entry chunk (warp 0)
        if (tid < 32) {
            int base = bestCh * 64;
            unsigned long long k1 = packkey(sc[base + tid],      (unsigned)(base + tid));
            unsigned long long k2 = packkey(sc[base + tid + 32], (unsigned)(base + tid + 32));
            unsigned long long kk = (k1 > k2) ? k1 : k2;
#pragma unroll
            for (int o = 16; o; o >>= 1) {
                unsigned long long other = __shfl_xor_sync(0xffffffffu, kk, o);
                if (other > kk) kk = other;
            }
            if (tid == 0) {
                int i = (int)(0xFFFFFFFFu - (unsigned)(kk & 0xFFFFFFFFull));
                unsigned u = (unsigned)(kk >> 32);
                u = (u & 0x80000000u) ? (u & 0x7FFFFFFFu) : ~u;
                sIdx[k] = i;
                sVal[k] = __uint_as_float(u);
                float4 bb = bx[i];
                float off = (float)((i >> 14) + 1) * offUnit;   // label * (max_coord+1)
                sPbox = make_float4(bb.x + off, bb.y + off, bb.z + off, bb.w + off);
                sOffv = off;
            }
        }
        __syncthreads();

        // --- suppression over the pick's class segment (16384 entries) ---
        const int i = sIdx[k];
        const int segBase = (i >> 14) << 14;
        const float off = sOffv;
        const float4 P = sPbox;
        const float pa = (P.z - P.x) * (P.w - P.y);

        const int ch = (segBase >> 6) + (tid >> 2);
        const int e0 = segBase + ((tid >> 2) << 6) + (tid & 3) * 16;
        float m = -INFINITY;
#pragma unroll 4
        for (int j = 0; j < 16; j++) {
            int idx = e0 + j;
            float s = sc[idx];
            if (s != -INFINITY) {
                float4 bb = bx[idx];
                float jx1 = bb.x + off, jy1 = bb.y + off;
                float jx2 = bb.z + off, jy2 = bb.w + off;
                float ix1 = fmaxf(P.x, jx1), iy1 = fmaxf(P.y, jy1);
                float ix2 = fminf(P.z, jx2), iy2 = fminf(P.w, jy2);
                float inter = fmaxf(ix2 - ix1, 0.0f) * fmaxf(iy2 - iy1, 0.0f);
                float jb = (jx2 - jx1) * (jy2 - jy1);
                float iou = inter / (pa + jb - inter + 1e-9f);
                if (iou > 0.5f || idx == i) { s = -INFINITY; sc[idx] = s; }
            }
            m = fmaxf(m, s);
        }
        // combine 4 partials per chunk (lanes grouped by 4)
        m = fmaxf(m, __shfl_xor_sync(0xffffffffu, m, 1));
        m = fmaxf(m, __shfl_xor_sync(0xffffffffu, m, 2));
        if ((tid & 3) == 0) chmax[ch] = m;
        __syncthreads();
    }

    // --- outputs: boxes[B,K,9] | scores[B,K] | labels[B,K] (float) ---
    const float* b9  = g_box9 + (size_t)f * CAND * 9;
    const float* raw = g_raw  + (size_t)f * CAND;
    for (int t = tid; t < NUM_K * 9; t += 1024) {
        int k = t / 9, j = t - k * 9;
        int i = sIdx[k];
        out[((size_t)f * NUM_K + k) * 9 + j] = b9[(size_t)i * 9 + j];
    }
    if (tid < NUM_K) {
        int i = sIdx[tid];
        bool pick = (sVal[tid] > -INFINITY);
        out[NUM_B * NUM_K * 9 + f * NUM_K + tid] = pick ? raw[i] : 0.0f;
        out[NUM_B * NUM_K * 9 + NUM_B * NUM_K + f * NUM_K + tid] =
            pick ? (float)((i >> 14) + 1) : -1.0f;
    }
}

// ---------------- launch ----------------
extern "C" void kernel_launch(void* const* d_in, const int* in_sizes, int n_in,
                              void* d_out, int out_size)
{
    const float* x  = (const float*)d_in[0];
    const float* pr = (const float*)d_in[1];
    const float* w1 = (const float*)d_in[2];
    const float* b1 = (const float*)d_in[3];
    const float* w2 = (const float*)d_in[4];
    const float* b2 = (const float*)d_in[5];
    const float* wc = (const float*)d_in[6];
    const float* bc = (const float*)d_in[7];
    const float* wr = (const float*)d_in[8];
    const float* br = (const float*)d_in[9];
    float* out = (float*)d_out;

    void *h1p, *h2p, *lgp, *rgp;
    cudaGetSymbolAddress(&h1p, g_h1);
    cudaGetSymbolAddress(&h2p, g_h2);
    cudaGetSymbolAddress(&lgp, g_logits);
    cudaGetSymbolAddress(&rgp, g_reg);

    // MLP: h1 = relu(x@w1+b1), h2 = relu(h1@w2+b2)
    gemm_bias_relu<<<dim3(NUM_H / BN, ROWS / BM), 256>>>(
        x, w1, b1, (float*)h1p, ROWS, NUM_DIN, NUM_H, 1);
    gemm_bias_relu<<<dim3(NUM_H / BN, ROWS / BM), 256>>>(
        (const float*)h1p, w2, b2, (float*)h2p, ROWS, NUM_H, NUM_H, 1);
    // heads: logits [ROWS,11], reg [ROWS,99]
    gemm_bias_relu<<<dim3(1, ROWS / BM), 256>>>(
        (const float*)h2p, wc, bc, (float*)lgp, ROWS, NUM_H, NUM_C, 0);
    gemm_bias_relu<<<dim3(2, ROWS / BM), 256>>>(
        (const float*)h2p, wr, br, (float*)rgp, ROWS, NUM_H, NUM_C * 9, 0);

    init_kernel<<<1, 1>>>();
    decode_kernel<<<(ROWS * (NUM_C - 1)) / 256, 256>>>(pr);
    nms_kernel<<<NUM_B, 1024>>>(out);
}

// round 6
// speedup vs baseline: 1.2305x; 1.2305x over previous
#include <cuda_runtime.h>
#include <math.h>
#include <stdint.h>

// Problem constants
#define NUM_B   2
#define NUM_N   16384
#define NUM_DIN 1024
#define NUM_H   512
#define NUM_C   11
#define NUM_K   100
#define CAND    (NUM_N * (NUM_C - 1))   // 163840 candidates per frame
#define NCHUNK  (CAND / 64)             // 2560 chunks of 64
#define ROWS    (NUM_B * NUM_N)         // 32768

// ---------------- scratch (static device globals; no allocs) ----------------
__device__ float g_h1[(size_t)ROWS * NUM_H];
__device__ float g_h2[(size_t)ROWS * NUM_H];
__device__ float g_logits[(size_t)ROWS * NUM_C];
__device__ float g_reg[(size_t)ROWS * NUM_C * 9];
__device__ float4 g_box4[NUM_B * CAND];                  // class-major layout
__device__ float  g_box9[(size_t)NUM_B * CAND * 9];
__device__ float  g_raw[NUM_B * CAND];
__device__ float  g_mask[NUM_B * CAND];
__device__ unsigned int g_maxbits;

// ---------------- packed f32x2 helpers (Blackwell FFMA2 path) ----------------
__device__ __forceinline__ unsigned long long pk2(float x) {
    unsigned long long r;
    asm("mov.b64 %0, {%1, %1};" : "=l"(r) : "r"(__float_as_uint(x)));
    return r;
}
__device__ __forceinline__ void fma2(unsigned long long& d,
                                     unsigned long long a, unsigned long long b) {
    asm("fma.rn.f32x2 %0, %1, %2, %0;" : "+l"(d) : "l"(a), "l"(b));
}
__device__ __forceinline__ void unpk2(float& lo, float& hi, unsigned long long v) {
    asm("mov.b64 {%0, %1}, %2;" : "=f"(lo), "=f"(hi) : "l"(v));
}

// ================= fast fp32 GEMM: 128x128 tile, 8x8 microtile, FFMA2 =======
// Requires: M % 128 == 0, N % 128 == 0, K % 16 == 0.
#define GBM 128
#define GBN 128
#define GBK 16

__global__ __launch_bounds__(256)
void gemm_f32x2(const float* __restrict__ A, const float* __restrict__ W,
                const float* __restrict__ bias, float* __restrict__ C,
                int M, int K, int N, int doRelu)
{
    __shared__ float As[GBK][GBM + 4];
    __shared__ float Ws[GBK][GBN];

    const int tid = threadIdx.x;
    const int bm = blockIdx.y * GBM;
    const int bn = blockIdx.x * GBN;
    const int tx = tid & 15;   // 0..15
    const int ty = tid >> 4;   // 0..15

    // A staging: 128 rows x 16 k = 512 float4; 2 per thread
    const int aRow0 = tid >> 2;          // 0..63
    const int aRow1 = aRow0 + 64;
    const int aC    = (tid & 3) * 4;     // 0,4,8,12
    // W staging: 16 rows x 128 cols = 512 float4; 2 per thread
    const int wRow0 = tid >> 5;          // 0..7
    const int wRow1 = wRow0 + 8;
    const int wC    = (tid & 31) * 4;    // 0..124

    const float* Ap0 = A + (size_t)(bm + aRow0) * K + aC;
    const float* Ap1 = A + (size_t)(bm + aRow1) * K + aC;
    const float* Wp0 = W + (size_t)wRow0 * N + bn + wC;
    const float* Wp1 = W + (size_t)wRow1 * N + bn + wC;

    unsigned long long acc[8][4];
#pragma unroll
    for (int i = 0; i < 8; i++)
#pragma unroll
        for (int j = 0; j < 4; j++) acc[i][j] = 0ull;

    // stage tile 0
    float4 a0 = *(const float4*)(Ap0);
    float4 a1 = *(const float4*)(Ap1);
    float4 w0 = *(const float4*)(Wp0);
    float4 w1 = *(const float4*)(Wp1);

    for (int k0 = 0; k0 < K; k0 += GBK) {
        // staged regs -> smem
        As[aC + 0][aRow0] = a0.x; As[aC + 1][aRow0] = a0.y;
        As[aC + 2][aRow0] = a0.z; As[aC + 3][aRow0] = a0.w;
        As[aC + 0][aRow1] = a1.x; As[aC + 1][aRow1] = a1.y;
        As[aC + 2][aRow1] = a1.z; As[aC + 3][aRow1] = a1.w;
        *(float4*)&Ws[wRow0][wC] = w0;
        *(float4*)&Ws[wRow1][wC] = w1;
        __syncthreads();

        // prefetch next tile into registers (overlaps with compute)
        if (k0 + GBK < K) {
            a0 = *(const float4*)(Ap0 + k0 + GBK);
            a1 = *(const float4*)(Ap1 + k0 + GBK);
            w0 = *(const float4*)(Wp0 + (size_t)(k0 + GBK) * N);
            w1 = *(const float4*)(Wp1 + (size_t)(k0 + GBK) * N);
        }

#pragma unroll
        for (int kk = 0; kk < GBK; kk++) {
            float4 aL = *(const float4*)&As[kk][ty * 4];
            float4 aH = *(const float4*)&As[kk][ty * 4 + 64];
            ulonglong2 bL = *(const ulonglong2*)&Ws[kk][tx * 4];
            ulonglong2 bH = *(const ulonglong2*)&Ws[kk][tx * 4 + 64];
            unsigned long long ap[8] = {
                pk2(aL.x), pk2(aL.y), pk2(aL.z), pk2(aL.w),
                pk2(aH.x), pk2(aH.y), pk2(aH.z), pk2(aH.w)};
            unsigned long long bp[4] = {bL.x, bL.y, bH.x, bH.y};
#pragma unroll
            for (int i = 0; i < 8; i++)
#pragma unroll
                for (int j = 0; j < 4; j++)
                    fma2(acc[i][j], ap[i], bp[j]);
        }
        __syncthreads();
    }

    // epilogue: rows ty*4+{0..3} and 64+ty*4+{0..3}; col pairs at tx*4 / tx*4+64
#pragma unroll
    for (int i = 0; i < 8; i++) {
        int row = bm + ty * 4 + ((i < 4) ? i : 64 + (i - 4));
        float* crow = C + (size_t)row * N;
#pragma unroll
        for (int j = 0; j < 4; j++) {
            int col = bn + tx * 4 + ((j < 2) ? 2 * j : 64 + 2 * (j - 2));
            float lo, hi;
            unpk2(lo, hi, acc[i][j]);
            lo += bias[col];
            hi += bias[col + 1];
            if (doRelu) { lo = fmaxf(lo, 0.0f); hi = fmaxf(hi, 0.0f); }
            *(float2*)&crow[col] = make_float2(lo, hi);
        }
    }
}

// ============ fused heads GEMM: [ROWS,512] @ [512,110] -> logits|reg ========
// cols 0..10 -> g_logits (stride 11), cols 11..109 -> g_reg (stride 99)
#define HBM 128
#define HBN 64
#define HBK 16

__global__ __launch_bounds__(256)
void head_gemm(const float* __restrict__ A,
               const float* __restrict__ wc, const float* __restrict__ bc,
               const float* __restrict__ wr, const float* __restrict__ br,
               float* __restrict__ logits, float* __restrict__ reg)
{
    __shared__ float As[HBK][HBM + 4];
    __shared__ float Ws[HBK][HBN];

    const int tid = threadIdx.x;
    const int bm = blockIdx.y * HBM;
    const int bn = blockIdx.x * HBN;
    const int tx = tid & 15;
    const int ty = tid >> 4;

    float acc[8][4];
#pragma unroll
    for (int i = 0; i < 8; i++)
#pragma unroll
        for (int j = 0; j < 4; j++) acc[i][j] = 0.0f;

    const int aRow = tid >> 2;
    const int aK   = (tid & 3) << 2;
    const int wRow = tid >> 4;
    const int wCol = (tid & 15) << 2;

    for (int k0 = 0; k0 < NUM_H; k0 += HBK) {
        float4 q0 = *(const float4*)(A + (size_t)(bm + aRow) * NUM_H + k0 + aK);
        float4 q1 = *(const float4*)(A + (size_t)(bm + aRow + 64) * NUM_H + k0 + aK);
        As[aK + 0][aRow] = q0.x; As[aK + 1][aRow] = q0.y;
        As[aK + 2][aRow] = q0.z; As[aK + 3][aRow] = q0.w;
        As[aK + 0][aRow + 64] = q1.x; As[aK + 1][aRow + 64] = q1.y;
        As[aK + 2][aRow + 64] = q1.z; As[aK + 3][aRow + 64] = q1.w;

#pragma unroll
        for (int j = 0; j < 4; j++) {
            int col = bn + wCol + j;
            float v = 0.0f;
            if (col < NUM_C)
                v = wc[(size_t)(k0 + wRow) * NUM_C + col];
            else if (col < NUM_C + NUM_C * 9 - 9)  // < 110
                v = wr[(size_t)(k0 + wRow) * (NUM_C * 9) + (col - NUM_C)];
            Ws[wRow][wCol + j] = v;
        }
        __syncthreads();

#pragma unroll
        for (int kk = 0; kk < HBK; kk++) {
            float4 aA = *(const float4*)&As[kk][ty * 8];
            float4 aB = *(const float4*)&As[kk][ty * 8 + 4];
            float4 bV = *(const float4*)&Ws[kk][tx * 4];
            float av[8] = {aA.x, aA.y, aA.z, aA.w, aB.x, aB.y, aB.z, aB.w};
            float bv[4] = {bV.x, bV.y, bV.z, bV.w};
#pragma unroll
            for (int i = 0; i < 8; i++)
#pragma unroll
                for (int j = 0; j < 4; j++)
                    acc[i][j] = fmaf(av[i], bv[j], acc[i][j]);
        }
        __syncthreads();
    }

#pragma unroll
    for (int i = 0; i < 8; i++) {
        int row = bm + ty * 8 + i;
#pragma unroll
        for (int j = 0; j < 4; j++) {
            int col = bn + tx * 4 + j;
            if (col < NUM_C) {
                logits[(size_t)row * NUM_C + col] = acc[i][j] + bc[col];
            } else if (col < 110) {
                reg[(size_t)row * (NUM_C * 9) + (col - NUM_C)] =
                    acc[i][j] + br[col - NUM_C];
            }
        }
    }
}

// ---------------- init ----------------
__global__ void init_kernel() { g_maxbits = 0u; }

// ---------------- softmax + box decode + candidate build ----------------
__global__ __launch_bounds__(256)
void decode_kernel(const float* __restrict__ proposals)
{
    const int tid = blockIdx.x * blockDim.x + threadIdx.x;   // < 327680
    const int c  = tid >> 15;        // class-1 index 0..9 (label = c+1)
    const int bn = tid & 32767;      // flat row
    const int b  = bn >> 14;
    const int n  = bn & 16383;

    // softmax over 11 logits
    const float* lrow = g_logits + (size_t)bn * NUM_C;
    float l[NUM_C];
#pragma unroll
    for (int i = 0; i < NUM_C; i++) l[i] = lrow[i];
    float m = l[0];
#pragma unroll
    for (int i = 1; i < NUM_C; i++) m = fmaxf(m, l[i]);
    float sum = 0.0f;
#pragma unroll
    for (int i = 0; i < NUM_C; i++) sum += expf(l[i] - m);
    float score = expf(l[c + 1] - m) / sum;

    // decode
    const float* p = proposals + (size_t)bn * 9;
    float w  = p[2] - p[0], h = p[3] - p[1];
    float cx = p[0] + 0.5f * w, cy = p[1] + 0.5f * h;
    const float* r = g_reg + (size_t)bn * (NUM_C * 9) + (c + 1) * 9;
    const float CLIP = 4.135166556742356f;  // log(1000/16)
    float dx = r[0] / 10.0f, dy = r[1] / 10.0f;
    float dw = fminf(r[2] / 5.0f, CLIP), dh = fminf(r[3] / 5.0f, CLIP);
    float pcx = dx * w + cx, pcy = dy * h + cy;
    float pw = expf(dw) * w, ph = expf(dh) * h;
    float x1 = pcx - 0.5f * pw, y1 = pcy - 0.5f * ph;
    float x2 = pcx + 0.5f * pw, y2 = pcy + 0.5f * ph;

    const int cand = b * CAND + c * NUM_N + n;   // class-major per frame
    g_box4[cand] = make_float4(x1, y1, x2, y2);
    float* b9 = g_box9 + (size_t)cand * 9;
    b9[0] = x1; b9[1] = y1; b9[2] = x2; b9[3] = y2;
#pragma unroll
    for (int j = 0; j < 5; j++) b9[4 + j] = p[4 + j] + r[4 + j];

    float bw = x2 - x1, bh = y2 - y1;
    bool valid = (score > 0.05f) && (bw >= 0.01f) && (bh >= 0.01f);
    g_raw[cand]  = score;
    g_mask[cand] = valid ? score : -INFINITY;

    // global max |coord| (order-independent => matches reference's max)
    float mc = fmaxf(fmaxf(fabsf(x1), fabsf(y1)), fmaxf(fabsf(x2), fabsf(y2)));
#pragma unroll
    for (int o = 16; o; o >>= 1)
        mc = fmaxf(mc, __shfl_xor_sync(0xffffffffu, mc, o));
    if ((threadIdx.x & 31) == 0) atomicMax(&g_maxbits, __float_as_uint(mc));
}

// ---------------- greedy NMS (exact), one block per frame ----------------
__device__ __forceinline__ unsigned long long packkey(float v, unsigned idx) {
    unsigned u = __float_as_uint(v);
    u = (u & 0x80000000u) ? ~u : (u | 0x80000000u);   // order-preserving float map
    return ((unsigned long long)u << 32) | (unsigned long long)(0xFFFFFFFFu - idx);
}

__global__ __launch_bounds__(1024)
void nms_kernel(float* __restrict__ out)
{
    const int f = blockIdx.x;
    const int tid = threadIdx.x;

    __shared__ float chmax[NCHUNK];
    __shared__ unsigned long long warpKeys[32];
    __shared__ unsigned long long sBestKey;
    __shared__ int   sIdx[NUM_K];
    __shared__ float sVal[NUM_K];
    __shared__ float4 sPbox;
    __shared__ float sOffv;

    float* sc = g_mask + (size_t)f * CAND;
    const float4* bx = g_box4 + (size_t)f * CAND;
    const float maxc = __uint_as_float(g_maxbits);
    const float offUnit = maxc + 1.0f;

    // build per-chunk maxima
    for (int ch = tid; ch < NCHUNK; ch += 1024) {
        const float4* p4 = (const float4*)(sc + ch * 64);
        float m = -INFINITY;
#pragma unroll
        for (int j = 0; j < 16; j++) {
            float4 v = p4[j];
            m = fmaxf(m, fmaxf(fmaxf(v.x, v.y), fmaxf(v.z, v.w)));
        }
        chmax[ch] = m;
    }
    __syncthreads();

    for (int k = 0; k < NUM_K; k++) {
        // --- hierarchical argmax (lowest index wins ties) ---
        unsigned long long key = 0ull;
        for (int ch = tid; ch < NCHUNK; ch += 1024) {
            unsigned long long kk = packkey(chmax[ch], (unsigned)ch);
            if (kk > key) key = kk;
        }
#pragma unroll
        for (int o = 16; o; o >>= 1) {
            unsigned long long other = __shfl_xor_sync(0xffffffffu, key, o);
            if (other > key) key = other;
        }
        if ((tid & 31) == 0) warpKeys[tid >> 5] = key;
        __syncthreads();
        if (tid < 32) {
            unsigned long long kk = warpKeys[tid];
#pragma unroll
            for (int o = 16; o; o >>= 1) {
                unsigned long long other = __shfl_xor_sync(0xffffffffu, kk, o);
                if (other > kk) kk = other;
            }
            if (tid == 0) sBestKey = kk;
        }
        __syncthreads();
        const int bestCh = (int)(0xFFFFFFFFu - (unsigned)(sBestKey & 0xFFFFFFFFull));

        // rescan winning 64-entry chunk (warp 0)
        if (tid < 32) {
            int base = bestCh * 64;
            unsigned long long k1 = packkey(sc[base + tid],      (unsigned)(base + tid));
            unsigned long long k2 = packkey(sc[base + tid + 32], (unsigned)(base + tid + 32));
            unsigned long long kk = (k1 > k2) ? k1 : k2;
#pragma unroll
            for (int o = 16; o; o >>= 1) {
                unsigned long long other = __shfl_xor_sync(0xffffffffu, kk, o);
                if (other > kk) kk = other;
            }
            if (tid == 0) {
                int i = (int)(0xFFFFFFFFu - (unsigned)(kk & 0xFFFFFFFFull));
                unsigned u = (unsigned)(kk >> 32);
                u = (u & 0x80000000u) ? (u & 0x7FFFFFFFu) : ~u;
                sIdx[k] = i;
                sVal[k] = __uint_as_float(u);
                float4 bb = bx[i];
                float off = (float)((i >> 14) + 1) * offUnit;   // label * (max_coord+1)
                sPbox = make_float4(bb.x + off, bb.y + off, bb.z + off, bb.w + off);
                sOffv = off;
            }
        }
        __syncthreads();

        // --- suppression over the pick's class segment (16384 entries) ---
        const int i = sIdx[k];
        const int segBase = (i >> 14) << 14;
        const float off = sOffv;
        const float4 P = sPbox;
        const float pa = (P.z - P.x) * (P.w - P.y);

        const int ch = (segBase >> 6) + (tid >> 2);
        const int e0 = segBase + ((tid >> 2) << 6) + (tid & 3) * 16;
        float m = -INFINITY;
#pragma unroll
        for (int q = 0; q < 4; q++) {
            int idx0 = e0 + q * 4;
            float4 s4 = *(const float4*)(sc + idx0);
            float sv[4] = {s4.x, s4.y, s4.z, s4.w};
#pragma unroll
            for (int u = 0; u < 4; u++) {
                int idx = idx0 + u;
                float s = sv[u];
                if (s != -INFINITY) {
                    float4 bb = bx[idx];
                    float jx1 = bb.x + off, jy1 = bb.y + off;
                    float jx2 = bb.z + off, jy2 = bb.w + off;
                    float ix1 = fmaxf(P.x, jx1), iy1 = fmaxf(P.y, jy1);
                    float ix2 = fminf(P.z, jx2), iy2 = fminf(P.w, jy2);
                    float inter = fmaxf(ix2 - ix1, 0.0f) * fmaxf(iy2 - iy1, 0.0f);
                    float jb = (jx2 - jx1) * (jy2 - jy1);
                    float iou = inter / (pa + jb - inter + 1e-9f);
                    if (iou > 0.5f || idx == i) { s = -INFINITY; sc[idx] = s; }
                }
                m = fmaxf(m, s);
            }
        }
        // combine 4 partials per chunk (lanes grouped by 4)
        m = fmaxf(m, __shfl_xor_sync(0xffffffffu, m, 1));
        m = fmaxf(m, __shfl_xor_sync(0xffffffffu, m, 2));
        if ((tid & 3) == 0) chmax[ch] = m;
        __syncthreads();
    }

    // --- outputs: boxes[B,K,9] | scores[B,K] | labels[B,K] (float) ---
    const float* b9  = g_box9 + (size_t)f * CAND * 9;
    const float* raw = g_raw  + (size_t)f * CAND;
    for (int t = tid; t < NUM_K * 9; t += 1024) {
        int k = t / 9, j = t - k * 9;
        int i = sIdx[k];
        out[((size_t)f * NUM_K + k) * 9 + j] = b9[(size_t)i * 9 + j];
    }
    if (tid < NUM_K) {
        int i = sIdx[tid];
        bool pick = (sVal[tid] > -INFINITY);
        out[NUM_B * NUM_K * 9 + f * NUM_K + tid] = pick ? raw[i] : 0.0f;
        out[NUM_B * NUM_K * 9 + NUM_B * NUM_K + f * NUM_K + tid] =
            pick ? (float)((i >> 14) + 1) : -1.0f;
    }
}

// ---------------- launch ----------------
extern "C" void kernel_launch(void* const* d_in, const int* in_sizes, int n_in,
                              void* d_out, int out_size)
{
    const float* x  = (const float*)d_in[0];
    const float* pr = (const float*)d_in[1];
    const float* w1 = (const float*)d_in[2];
    const float* b1 = (const float*)d_in[3];
    const float* w2 = (const float*)d_in[4];
    const float* b2 = (const float*)d_in[5];
    const float* wc = (const float*)d_in[6];
    const float* bc = (const float*)d_in[7];
    const float* wr = (const float*)d_in[8];
    const float* br = (const float*)d_in[9];
    float* out = (float*)d_out;

    void *h1p, *h2p, *lgp, *rgp;
    cudaGetSymbolAddress(&h1p, g_h1);
    cudaGetSymbolAddress(&h2p, g_h2);
    cudaGetSymbolAddress(&lgp, g_logits);
    cudaGetSymbolAddress(&rgp, g_reg);

    // MLP: h1 = relu(x@w1+b1), h2 = relu(h1@w2+b2)  — FFMA2 path
    gemm_f32x2<<<dim3(NUM_H / GBN, ROWS / GBM), 256>>>(
        x, w1, b1, (float*)h1p, ROWS, NUM_DIN, NUM_H, 1);
    gemm_f32x2<<<dim3(NUM_H / GBN, ROWS / GBM), 256>>>(
        (const float*)h1p, w2, b2, (float*)h2p, ROWS, NUM_H, NUM_H, 1);

    // fused heads: logits [ROWS,11] + reg [ROWS,99] in one launch
    head_gemm<<<dim3(2, ROWS / HBM), 256>>>(
        (const float*)h2p, wc, bc, wr, br, (float*)lgp, (float*)rgp);

    init_kernel<<<1, 1>>>();
    decode_kernel<<<(ROWS * (NUM_C - 1)) / 256, 256>>>(pr);
    nms_kernel<<<NUM_B, 1024>>>(out);
}

// round 7
// speedup vs baseline: 1.2331x; 1.0021x over previous
#include <cuda_runtime.h>
#include <math.h>
#include <stdint.h>

// Problem constants
#define NUM_B   2
#define NUM_N   16384
#define NUM_DIN 1024
#define NUM_H   512
#define NUM_C   11
#define NUM_K   100
#define CAND    (NUM_N * (NUM_C - 1))   // 163840 candidates per frame
#define NCHUNK  (CAND / 64)             // 2560 chunks of 64
#define ROWS    (NUM_B * NUM_N)         // 32768

// ---------------- scratch (static device globals; no allocs) ----------------
__device__ float g_h1[(size_t)ROWS * NUM_H];
__device__ float g_h2[(size_t)ROWS * NUM_H];
__device__ float g_logits[(size_t)ROWS * NUM_C];
__device__ float g_reg[(size_t)ROWS * NUM_C * 9];
__device__ float4 g_box4[NUM_B * CAND];                  // class-major layout
__device__ float  g_box9[(size_t)NUM_B * CAND * 9];
__device__ float  g_raw[NUM_B * CAND];
__device__ float  g_mask[NUM_B * CAND];
__device__ unsigned int g_maxbits;

// ---------------- packed f32x2 helpers (Blackwell FFMA2 path) ----------------
__device__ __forceinline__ unsigned long long pk2(float x) {
    unsigned long long r;
    asm("mov.b64 %0, {%1, %1};" : "=l"(r) : "r"(__float_as_uint(x)));
    return r;
}
__device__ __forceinline__ void fma2(unsigned long long& d,
                                     unsigned long long a, unsigned long long b) {
    asm("fma.rn.f32x2 %0, %1, %2, %0;" : "+l"(d) : "l"(a), "l"(b));
}
__device__ __forceinline__ void unpk2(float& lo, float& hi, unsigned long long v) {
    asm("mov.b64 {%0, %1}, %2;" : "=f"(lo), "=f"(hi) : "l"(v));
}

// ================= fast fp32 GEMM: 128x128 tile, 8x8 microtile, FFMA2 =======
// Requires: M % 128 == 0, N % 128 == 0, K % 16 == 0.
#define GBM 128
#define GBN 128
#define GBK 16

__global__ __launch_bounds__(256)
void gemm_f32x2(const float* __restrict__ A, const float* __restrict__ W,
                const float* __restrict__ bias, float* __restrict__ C,
                int M, int K, int N, int doRelu)
{
    __shared__ float As[GBK][GBM + 4];
    __shared__ float Ws[GBK][GBN];

    const int tid = threadIdx.x;
    const int bm = blockIdx.y * GBM;
    const int bn = blockIdx.x * GBN;
    const int tx = tid & 15;   // 0..15
    const int ty = tid >> 4;   // 0..15

    // A staging: 128 rows x 16 k = 512 float4; 2 per thread
    const int aRow0 = tid >> 2;          // 0..63
    const int aRow1 = aRow0 + 64;
    const int aC    = (tid & 3) * 4;     // 0,4,8,12
    // W staging: 16 rows x 128 cols = 512 float4; 2 per thread
    const int wRow0 = tid >> 5;          // 0..7
    const int wRow1 = wRow0 + 8;
    const int wC    = (tid & 31) * 4;    // 0..124

    const float* Ap0 = A + (size_t)(bm + aRow0) * K + aC;
    const float* Ap1 = A + (size_t)(bm + aRow1) * K + aC;
    const float* Wp0 = W + (size_t)wRow0 * N + bn + wC;
    const float* Wp1 = W + (size_t)wRow1 * N + bn + wC;

    unsigned long long acc[8][4];
#pragma unroll
    for (int i = 0; i < 8; i++)
#pragma unroll
        for (int j = 0; j < 4; j++) acc[i][j] = 0ull;

    // stage tile 0
    float4 a0 = *(const float4*)(Ap0);
    float4 a1 = *(const float4*)(Ap1);
    float4 w0 = *(const float4*)(Wp0);
    float4 w1 = *(const float4*)(Wp1);

    for (int k0 = 0; k0 < K; k0 += GBK) {
        // staged regs -> smem
        As[aC + 0][aRow0] = a0.x; As[aC + 1][aRow0] = a0.y;
        As[aC + 2][aRow0] = a0.z; As[aC + 3][aRow0] = a0.w;
        As[aC + 0][aRow1] = a1.x; As[aC + 1][aRow1] = a1.y;
        As[aC + 2][aRow1] = a1.z; As[aC + 3][aRow1] = a1.w;
        *(float4*)&Ws[wRow0][wC] = w0;
        *(float4*)&Ws[wRow1][wC] = w1;
        __syncthreads();

        // prefetch next tile into registers (overlaps with compute)
        if (k0 + GBK < K) {
            a0 = *(const float4*)(Ap0 + k0 + GBK);
            a1 = *(const float4*)(Ap1 + k0 + GBK);
            w0 = *(const float4*)(Wp0 + (size_t)(k0 + GBK) * N);
            w1 = *(const float4*)(Wp1 + (size_t)(k0 + GBK) * N);
        }

#pragma unroll
        for (int kk = 0; kk < GBK; kk++) {
            float4 aL = *(const float4*)&As[kk][ty * 4];
            float4 aH = *(const float4*)&As[kk][ty * 4 + 64];
            ulonglong2 bL = *(const ulonglong2*)&Ws[kk][tx * 4];
            ulonglong2 bH = *(const ulonglong2*)&Ws[kk][tx * 4 + 64];
            unsigned long long ap[8] = {
                pk2(aL.x), pk2(aL.y), pk2(aL.z), pk2(aL.w),
                pk2(aH.x), pk2(aH.y), pk2(aH.z), pk2(aH.w)};
            unsigned long long bp[4] = {bL.x, bL.y, bH.x, bH.y};
#pragma unroll
            for (int i = 0; i < 8; i++)
#pragma unroll
                for (int j = 0; j < 4; j++)
                    fma2(acc[i][j], ap[i], bp[j]);
        }
        __syncthreads();
    }

    // epilogue: rows ty*4+{0..3} and 64+ty*4+{0..3}; col pairs at tx*4 / tx*4+64
#pragma unroll
    for (int i = 0; i < 8; i++) {
        int row = bm + ty * 4 + ((i < 4) ? i : 64 + (i - 4));
        float* crow = C + (size_t)row * N;
#pragma unroll
        for (int j = 0; j < 4; j++) {
            int col = bn + tx * 4 + ((j < 2) ? 2 * j : 64 + 2 * (j - 2));
            float lo, hi;
            unpk2(lo, hi, acc[i][j]);
            lo += bias[col];
            hi += bias[col + 1];
            if (doRelu) { lo = fmaxf(lo, 0.0f); hi = fmaxf(hi, 0.0f); }
            *(float2*)&crow[col] = make_float2(lo, hi);
        }
    }
}

// ============ fused heads GEMM: [ROWS,512] @ [512,110] -> logits|reg ========
// cols 0..10 -> g_logits (stride 11), cols 11..109 -> g_reg (stride 99)
#define HBM 128
#define HBN 64
#define HBK 16

__global__ __launch_bounds__(256)
void head_gemm(const float* __restrict__ A,
               const float* __restrict__ wc, const float* __restrict__ bc,
               const float* __restrict__ wr, const float* __restrict__ br,
               float* __restrict__ logits, float* __restrict__ reg)
{
    __shared__ float As[HBK][HBM + 4];
    __shared__ float Ws[HBK][HBN];

    const int tid = threadIdx.x;
    const int bm = blockIdx.y * HBM;
    const int bn = blockIdx.x * HBN;
    const int tx = tid & 15;
    const int ty = tid >> 4;

    float acc[8][4];
#pragma unroll
    for (int i = 0; i < 8; i++)
#pragma unroll
        for (int j = 0; j < 4; j++) acc[i][j] = 0.0f;

    const int aRow = tid >> 2;
    const int aK   = (tid & 3) << 2;
    const int wRow = tid >> 4;
    const int wCol = (tid & 15) << 2;

    for (int k0 = 0; k0 < NUM_H; k0 += HBK) {
        float4 q0 = *(const float4*)(A + (size_t)(bm + aRow) * NUM_H + k0 + aK);
        float4 q1 = *(const float4*)(A + (size_t)(bm + aRow + 64) * NUM_H + k0 + aK);
        As[aK + 0][aRow] = q0.x; As[aK + 1][aRow] = q0.y;
        As[aK + 2][aRow] = q0.z; As[aK + 3][aRow] = q0.w;
        As[aK + 0][aRow + 64] = q1.x; As[aK + 1][aRow + 64] = q1.y;
        As[aK + 2][aRow + 64] = q1.z; As[aK + 3][aRow + 64] = q1.w;

#pragma unroll
        for (int j = 0; j < 4; j++) {
            int col = bn + wCol + j;
            float v = 0.0f;
            if (col < NUM_C)
                v = wc[(size_t)(k0 + wRow) * NUM_C + col];
            else if (col < NUM_C + NUM_C * 9 - 9)  // < 110
                v = wr[(size_t)(k0 + wRow) * (NUM_C * 9) + (col - NUM_C)];
            Ws[wRow][wCol + j] = v;
        }
        __syncthreads();

#pragma unroll
        for (int kk = 0; kk < HBK; kk++) {
            float4 aA = *(const float4*)&As[kk][ty * 8];
            float4 aB = *(const float4*)&As[kk][ty * 8 + 4];
            float4 bV = *(const float4*)&Ws[kk][tx * 4];
            float av[8] = {aA.x, aA.y, aA.z, aA.w, aB.x, aB.y, aB.z, aB.w};
            float bv[4] = {bV.x, bV.y, bV.z, bV.w};
#pragma unroll
            for (int i = 0; i < 8; i++)
#pragma unroll
                for (int j = 0; j < 4; j++)
                    acc[i][j] = fmaf(av[i], bv[j], acc[i][j]);
        }
        __syncthreads();
    }

#pragma unroll
    for (int i = 0; i < 8; i++) {
        int row = bm + ty * 8 + i;
#pragma unroll
        for (int j = 0; j < 4; j++) {
            int col = bn + tx * 4 + j;
            if (col < NUM_C) {
                logits[(size_t)row * NUM_C + col] = acc[i][j] + bc[col];
            } else if (col < 110) {
                reg[(size_t)row * (NUM_C * 9) + (col - NUM_C)] =
                    acc[i][j] + br[col - NUM_C];
            }
        }
    }
}

// ---------------- init ----------------
__global__ void init_kernel() { g_maxbits = 0u; }

// ---------------- softmax + box decode + candidate build ----------------
__global__ __launch_bounds__(256)
void decode_kernel(const float* __restrict__ proposals)
{
    const int tid = blockIdx.x * blockDim.x + threadIdx.x;   // < 327680
    const int c  = tid >> 15;        // class-1 index 0..9 (label = c+1)
    const int bn = tid & 32767;      // flat row
    const int b  = bn >> 14;
    const int n  = bn & 16383;

    // softmax over 11 logits
    const float* lrow = g_logits + (size_t)bn * NUM_C;
    float l[NUM_C];
#pragma unroll
    for (int i = 0; i < NUM_C; i++) l[i] = lrow[i];
    float m = l[0];
#pragma unroll
    for (int i = 1; i < NUM_C; i++) m = fmaxf(m, l[i]);
    float sum = 0.0f;
#pragma unroll
    for (int i = 0; i < NUM_C; i++) sum += expf(l[i] - m);
    float score = expf(l[c + 1] - m) / sum;

    // decode
    const float* p = proposals + (size_t)bn * 9;
    float w  = p[2] - p[0], h = p[3] - p[1];
    float cx = p[0] + 0.5f * w, cy = p[1] + 0.5f * h;
    const float* r = g_reg + (size_t)bn * (NUM_C * 9) + (c + 1) * 9;
    const float CLIP = 4.135166556742356f;  // log(1000/16)
    float dx = r[0] / 10.0f, dy = r[1] / 10.0f;
    float dw = fminf(r[2] / 5.0f, CLIP), dh = fminf(r[3] / 5.0f, CLIP);
    float pcx = dx * w + cx, pcy = dy * h + cy;
    float pw = expf(dw) * w, ph = expf(dh) * h;
    float x1 = pcx - 0.5f * pw, y1 = pcy - 0.5f * ph;
    float x2 = pcx + 0.5f * pw, y2 = pcy + 0.5f * ph;

    const int cand = b * CAND + c * NUM_N + n;   // class-major per frame
    g_box4[cand] = make_float4(x1, y1, x2, y2);
    float* b9 = g_box9 + (size_t)cand * 9;
    b9[0] = x1; b9[1] = y1; b9[2] = x2; b9[3] = y2;
#pragma unroll
    for (int j = 0; j < 5; j++) b9[4 + j] = p[4 + j] + r[4 + j];

    float bw = x2 - x1, bh = y2 - y1;
    bool valid = (score > 0.05f) && (bw >= 0.01f) && (bh >= 0.01f);
    g_raw[cand]  = score;
    g_mask[cand] = valid ? score : -INFINITY;

    // global max |coord| (order-independent => matches reference's max)
    float mc = fmaxf(fmaxf(fabsf(x1), fabsf(y1)), fmaxf(fabsf(x2), fabsf(y2)));
#pragma unroll
    for (int o = 16; o; o >>= 1)
        mc = fmaxf(mc, __shfl_xor_sync(0xffffffffu, mc, o));
    if ((threadIdx.x & 31) == 0) atomicMax(&g_maxbits, __float_as_uint(mc));
}

// ---------------- greedy NMS (exact), one block per frame ----------------
__device__ __forceinline__ unsigned long long packkey(float v, unsigned idx) {
    unsigned u = __float_as_uint(v);
    u = (u & 0x80000000u) ? ~u : (u | 0x80000000u);   // order-preserving float map
    return ((unsigned long long)u << 32) | (unsigned long long)(0xFFFFFFFFu - idx);
}

__global__ __launch_bounds__(1024)
void nms_kernel(float* __restrict__ out)
{
    const int f = blockIdx.x;
    const int tid = threadIdx.x;

    __shared__ float chmax[NCHUNK];
    __shared__ unsigned long long warpKeys[32];
    __shared__ unsigned long long sBestKey;
    __shared__ int   sIdx[NUM_K];
    __shared__ float sVal[NUM_K];
    __shared__ float4 sPbox;
    __shared__ float sOffv;

    float* sc = g_mask + (size_t)f * CAND;
    const float4* bx = g_box4 + (size_t)f * CAND;
    const float maxc = __uint_as_float(g_maxbits);
    const float offUnit = maxc + 1.0f;

    // build per-chunk maxima
    for (int ch = tid; ch < NCHUNK; ch += 1024) {
        const float4* p4 = (const float4*)(sc + ch * 64);
        float m = -INFINITY;
#pragma unroll
        for (int j = 0; j < 16; j++) {
            float4 v = p4[j];
            m = fmaxf(m, fmaxf(fmaxf(v.x, v.y), fmaxf(v.z, v.w)));
        }
        chmax[ch] = m;
    }
    __syncthreads();

    for (int k = 0; k < NUM_K; k++) {
        // --- hierarchical argmax (lowest index wins ties) ---
        unsigned long long key = 0ull;
        for (int ch = tid; ch < NCHUNK; ch += 1024) {
            unsigned long long kk = packkey(chmax[ch], (unsigned)ch);
            if (kk > key) key = kk;
        }
#pragma unroll
        for (int o = 16; o; o >>= 1) {
            unsigned long long other = __shfl_xor_sync(0xffffffffu, key, o);
            if (other > key) key = other;
        }
        if ((tid & 31) == 0) warpKeys[tid >> 5] = key;
        __syncthreads();
        if (tid < 32) {
            unsigned long long kk = warpKeys[tid];
#pragma unroll
            for (int o = 16; o; o >>= 1) {
                unsigned long long other = __shfl_xor_sync(0xffffffffu, kk, o);
                if (other > kk) kk = other;
            }
            if (tid == 0) sBestKey = kk;
        }
        __syncthreads();
        const int bestCh = (int)(0xFFFFFFFFu - (unsigned)(sBestKey & 0xFFFFFFFFull));

        // rescan winning 64-entry chunk (warp 0)
        if (tid < 32) {
            int base = bestCh * 64;
            unsigned long long k1 = packkey(sc[base + tid],      (unsigned)(base + tid));
            unsigned long long k2 = packkey(sc[base + tid + 32], (unsigned)(base + tid + 32));
            unsigned long long kk = (k1 > k2) ? k1 : k2;
#pragma unroll
            for (int o = 16; o; o >>= 1) {
                unsigned long long other = __shfl_xor_sync(0xffffffffu, kk, o);
                if (other > kk) kk = other;
            }
            if (tid == 0) {
                int i = (int)(0xFFFFFFFFu - (unsigned)(kk & 0xFFFFFFFFull));
                unsigned u = (unsigned)(kk >> 32);
                u = (u & 0x80000000u) ? (u & 0x7FFFFFFFu) : ~u;
                sIdx[k] = i;
                sVal[k] = __uint_as_float(u);
                float4 bb = bx[i];
                float off = (float)((i >> 14) + 1) * offUnit;   // label * (max_coord+1)
                sPbox = make_float4(bb.x + off, bb.y + off, bb.z + off, bb.w + off);
                sOffv = off;
            }
        }
        __syncthreads();

        // --- suppression over the pick's class segment (16384 entries) ---
        const int i = sIdx[k];
        const int segBase = (i >> 14) << 14;
        const float off = sOffv;
        const float4 P = sPbox;
        const float pa = (P.z - P.x) * (P.w - P.y);

        const int ch = (segBase >> 6) + (tid >> 2);
        const int e0 = segBase + ((tid >> 2) << 6) + (tid & 3) * 16;
        float m = -INFINITY;
#pragma unroll
        for (int q = 0; q < 4; q++) {
            int idx0 = e0 + q * 4;
            float4 s4 = *(const float4*)(sc + idx0);
            float sv[4] = {s4.x, s4.y, s4.z, s4.w};
#pragma unroll
            for (int u = 0; u < 4; u++) {
                int idx = idx0 + u;
                float s = sv[u];
                if (s != -INFINITY) {
                    float4 bb = bx[idx];
                    float jx1 = bb.x + off, jy1 = bb.y + off;
                    float jx2 = bb.z + off, jy2 = bb.w + off;
                    float ix1 = fmaxf(P.x, jx1), iy1 = fmaxf(P.y, jy1);
                    float ix2 = fminf(P.z, jx2), iy2 = fminf(P.w, jy2);
                    float inter = fmaxf(ix2 - ix1, 0.0f) * fmaxf(iy2 - iy1, 0.0f);
                    float jb = (jx2 - jx1) * (jy2 - jy1);
                    float iou = inter / (pa + jb - inter + 1e-9f);
                    if (iou > 0.5f || idx == i) { s = -INFINITY; sc[idx] = s; }
                }
                m = fmaxf(m, s);
            }
        }
        // combine 4 partials per chunk (lanes grouped by 4)
        m = fmaxf(m, __shfl_xor_sync(0xffffffffu, m, 1));
        m = fmaxf(m, __shfl_xor_sync(0xffffffffu, m, 2));
        if ((tid & 3) == 0) chmax[ch] = m;
        __syncthreads();
    }

    // --- outputs: boxes[B,K,9] | scores[B,K] | labels[B,K] (float) ---
    const float* b9  = g_box9 + (size_t)f * CAND * 9;
    const float* raw = g_raw  + (size_t)f * CAND;
    for (int t = tid; t < NUM_K * 9; t += 1024) {
        int k = t / 9, j = t - k * 9;
        int i = sIdx[k];
        out[((size_t)f * NUM_K + k) * 9 + j] = b9[(size_t)i * 9 + j];
    }
    if (tid < NUM_K) {
        int i = sIdx[tid];
        bool pick = (sVal[tid] > -INFINITY);
        out[NUM_B * NUM_K * 9 + f * NUM_K + tid] = pick ? raw[i] : 0.0f;
        out[NUM_B * NUM_K * 9 + NUM_B * NUM_K + f * NUM_K + tid] =
            pick ? (float)((i >> 14) + 1) : -1.0f;
    }
}

// ---------------- launch ----------------
extern "C" void kernel_launch(void* const* d_in, const int* in_sizes, int n_in,
                              void* d_out, int out_size)
{
    const float* x  = (const float*)d_in[0];
    const float* pr = (const float*)d_in[1];
    const float* w1 = (const float*)d_in[2];
    const float* b1 = (const float*)d_in[3];
    const float* w2 = (const float*)d_in[4];
    const float* b2 = (const float*)d_in[5];
    const float* wc = (const float*)d_in[6];
    const float* bc = (const float*)d_in[7];
    const float* wr = (const float*)d_in[8];
    const float* br = (const float*)d_in[9];
    float* out = (float*)d_out;

    void *h1p, *h2p, *lgp, *rgp;
    cudaGetSymbolAddress(&h1p, g_h1);
    cudaGetSymbolAddress(&h2p, g_h2);
    cudaGetSymbolAddress(&lgp, g_logits);
    cudaGetSymbolAddress(&rgp, g_reg);

    // MLP: h1 = relu(x@w1+b1), h2 = relu(h1@w2+b2)  — FFMA2 path
    gemm_f32x2<<<dim3(NUM_H / GBN, ROWS / GBM), 256>>>(
        x, w1, b1, (float*)h1p, ROWS, NUM_DIN, NUM_H, 1);
    gemm_f32x2<<<dim3(NUM_H / GBN, ROWS / GBM), 256>>>(
        (const float*)h1p, w2, b2, (float*)h2p, ROWS, NUM_H, NUM_H, 1);

    // fused heads: logits [ROWS,11] + reg [ROWS,99] in one launch
    head_gemm<<<dim3(2, ROWS / HBM), 256>>>(
        (const float*)h2p, wc, bc, wr, br, (float*)lgp, (float*)rgp);

    init_kernel<<<1, 1>>>();
    decode_kernel<<<(ROWS * (NUM_C - 1)) / 256, 256>>>(pr);
    nms_kernel<<<NUM_B, 1024>>>(out);
}